// round 8
// baseline (speedup 1.0000x reference)
#include <cuda_runtime.h>
#include <math.h>

#define HID     256
#define SLOTS   64
#define NB      4
#define TSTEPS  256
#define BATCH   512
#define WSROWS  192          // W rows in SMEM; rows 192-255 via LDG (warps 6,7)
#define NTH     256
#define EPSV    1e-5f

// Slot-memory scratch: 512 x 64 x 256 fp32 = 32 MB (L2-resident)
__device__ float g_mem[(size_t)BATCH * SLOTS * HID];

__device__ __forceinline__ float fast_tanh(float x) {
    float e = __expf(2.0f * x);
    return 1.0f - __fdividef(2.0f, e + 1.0f);
}

#define FFMA2(acc, a, b) \
    asm("fma.rn.f32x2 %0, %1, %2, %0;" : "+l"(acc) : "l"(a), "l"(b))

__global__ void __launch_bounds__(NTH, 1)
postnorm_rnn_kernel(const float* __restrict__ x,        // [512,256,1]
                    const float* __restrict__ W_embed,  // [256]
                    const float* __restrict__ b_embed,  // [256]
                    const float* __restrict__ W_update, // [256,256]
                    const float* __restrict__ b_update, // [256]
                    const float* __restrict__ gamma,    // [256]
                    const float* __restrict__ beta,     // [256]
                    const float* __restrict__ W_out,    // [10,256]
                    const float* __restrict__ b_out,    // [10]
                    const float* __restrict__ cs_in,    // [1]
                    float* __restrict__ out)            // [512,10]
{
    extern __shared__ float smem[];
    float* sW   = smem;                          // 192*256 dense = 49152 f
    float* vrow = sW + WSROWS * HID;             // [b][j] 4*256  =  1024 f
    float* xsm  = vrow + NB * HID;               // [b][t] 4*256  =  1024 f
    float* wtab = xsm + NB * TSTEPS;             // 64*5          =   320 f
    float* red  = wtab + 320;                    // 8 warps x 8   =    64 f
    float* osm  = red + 64;                      // 160*4         =   640 f

    const int tid  = threadIdx.x;
    const int i    = tid;                 // hidden index owned (phase1/LN/mem)
    const int b0   = blockIdx.x * NB;
    const int warp = tid >> 5;
    const int lane = tid & 31;
    const int s    = tid & 7;             // k-slice id (8 slices of 32 k)
    const int rb   = tid & ~7;            // row block: rows rb..rb+7
    const int sK   = s * 4;               // k offset within each 32-float group

    // ---- zero this CTA's slot-memory slice ----
    {
        float4* mz = (float4*)(g_mem + (size_t)b0 * SLOTS * HID);
        for (int k = tid; k < NB * SLOTS * HID / 4; k += NTH)
            mz[k] = make_float4(0.f, 0.f, 0.f, 0.f);
    }
    // ---- stage W_update rows [0,192) dense into SMEM ----
    {
        const float4* Wg = (const float4*)W_update;
        float4*       Ws = (float4*)sW;
        for (int idx = tid; idx < WSROWS * (HID / 4); idx += NTH)
            Ws[idx] = Wg[idx];
    }
    // ---- stage x: xsm[b][t] ----
    {
        int b = tid >> 6, t4 = tid & 63;
        ((float4*)xsm)[tid] =
            ((const float4*)(x + (size_t)(b0 + b) * TSTEPS))[t4];
    }
    // ---- precompute softmax attention-weight table ----
    if (tid < SLOTS) {
        int base = tid;
        float e[5], sum = 0.f;
#pragma unroll
        for (int k = 0; k < 5; k++) {
            int ix = (base + k - 2 + SLOTS) & (SLOTS - 1);
            float d = (float)(ix - base);
            e[k] = expf(-0.125f * d * d);
            sum += e[k];
        }
        float inv = 1.0f / sum;
#pragma unroll
        for (int k = 0; k < 5; k++) wtab[base * 5 + k] = e[k] * inv;
    }

    const float cs   = 1.0f / (1.0f + expf(-cs_in[0]));
    const float We_i = W_embed[i];
    const float be_i = b_embed[i];
    const float bu_i = b_update[i];
    const float g_i  = gamma[i];
    const float bt_i = beta[i];

    float h[NB];
    float m[NB][5];
    float* col[NB];
#pragma unroll
    for (int b = 0; b < NB; b++) {
        h[b] = 0.f;
        col[b] = g_mem + (size_t)(b0 + b) * SLOTS * HID + i;
#pragma unroll
        for (int k = 0; k < 5; k++) m[b][k] = 0.f;
    }

    const bool insm = (rb < WSROWS);      // uniform per warp (rows 192+ = warps 6,7)
    const float* wbase = insm ? (sW + rb * HID + sK)
                              : (W_update + (size_t)rb * HID + sK);

    __syncthreads();

    for (int t = 0; t < TSTEPS; t++) {
        const int base  = t & (SLOTS - 1);
        const int s_in  = ((base + 3)  & (SLOTS - 1)) * HID;
        const int s_out = ((base + 62) & (SLOTS - 1)) * HID;

        float pf[NB];
#pragma unroll
        for (int b = 0; b < NB; b++) pf[b] = col[b][s_in];

        float wn[5];
#pragma unroll
        for (int k = 0; k < 5; k++) wn[k] = wtab[base * 5 + k];

        // ---- phase 1: v[b] = tanh(x*We+be) + cs*ctx + h[b] ----
#pragma unroll
        for (int b = 0; b < NB; b++) {
            float ctx = 0.f;
#pragma unroll
            for (int k = 0; k < 5; k++) ctx = fmaf(wn[k], m[b][k], ctx);
            vrow[b * HID + i] =
                fast_tanh(fmaf(xsm[b * TSTEPS + t], We_i, be_i)) + cs * ctx + h[b];
        }
        __syncthreads();

        // ---- phase 2: rows rb..rb+7 x 4 batches over k-slice {32jj + 4s + e} ----
        unsigned long long acc[8][4];
#pragma unroll
        for (int r = 0; r < 8; r++)
#pragma unroll
            for (int b = 0; b < 4; b++) acc[r][b] = 0ull;

        if (insm) {
#pragma unroll 1
            for (int jj = 0; jj < 8; jj++) {
                const int off = jj * 32;
                ulonglong2 v0 = *(const ulonglong2*)(vrow + 0 * HID + sK + off);
                ulonglong2 v1 = *(const ulonglong2*)(vrow + 1 * HID + sK + off);
                ulonglong2 v2 = *(const ulonglong2*)(vrow + 2 * HID + sK + off);
                ulonglong2 v3 = *(const ulonglong2*)(vrow + 3 * HID + sK + off);
#pragma unroll
                for (int r = 0; r < 8; r++) {
                    ulonglong2 w2 = *(const ulonglong2*)(wbase + r * HID + off);
                    FFMA2(acc[r][0], w2.x, v0.x); FFMA2(acc[r][0], w2.y, v0.y);
                    FFMA2(acc[r][1], w2.x, v1.x); FFMA2(acc[r][1], w2.y, v1.y);
                    FFMA2(acc[r][2], w2.x, v2.x); FFMA2(acc[r][2], w2.y, v2.y);
                    FFMA2(acc[r][3], w2.x, v3.x); FFMA2(acc[r][3], w2.y, v3.y);
                }
            }
        } else {
#pragma unroll 1
            for (int jj = 0; jj < 8; jj++) {
                const int off = jj * 32;
                ulonglong2 v0 = *(const ulonglong2*)(vrow + 0 * HID + sK + off);
                ulonglong2 v1 = *(const ulonglong2*)(vrow + 1 * HID + sK + off);
                ulonglong2 v2 = *(const ulonglong2*)(vrow + 2 * HID + sK + off);
                ulonglong2 v3 = *(const ulonglong2*)(vrow + 3 * HID + sK + off);
#pragma unroll
                for (int r = 0; r < 8; r++) {
                    ulonglong2 w2 = __ldg((const ulonglong2*)(wbase + r * HID + off));
                    FFMA2(acc[r][0], w2.x, v0.x); FFMA2(acc[r][0], w2.y, v0.y);
                    FFMA2(acc[r][1], w2.x, v1.x); FFMA2(acc[r][1], w2.y, v1.y);
                    FFMA2(acc[r][2], w2.x, v2.x); FFMA2(acc[r][2], w2.y, v2.y);
                    FFMA2(acc[r][3], w2.x, v3.x); FFMA2(acc[r][3], w2.y, v3.y);
                }
            }
        }

        // ---- unpack partials: P[r][b] over this thread's 32-k slice ----
        float P[8][4];
#pragma unroll
        for (int r = 0; r < 8; r++)
#pragma unroll
            for (int b = 0; b < 4; b++) {
                float lo = __uint_as_float((unsigned)(acc[r][b] & 0xffffffffu));
                float hi = __uint_as_float((unsigned)(acc[r][b] >> 32));
                P[r][b] = lo + hi;
            }

        // ---- routed butterfly over the 8 k-slices: lane ends with row rb+s ----
        const bool h4 = (s & 4), h2 = (s & 2), h1 = (s & 1);
        float Q[4][4];
#pragma unroll
        for (int r = 0; r < 4; r++)
#pragma unroll
            for (int b = 0; b < 4; b++) {
                float keep = h4 ? P[r + 4][b] : P[r][b];
                float send = h4 ? P[r][b]     : P[r + 4][b];
                Q[r][b] = keep + __shfl_xor_sync(0xffffffffu, send, 4);
            }
        float R2[2][4];
#pragma unroll
        for (int r = 0; r < 2; r++)
#pragma unroll
            for (int b = 0; b < 4; b++) {
                float keep = h2 ? Q[r + 2][b] : Q[r][b];
                float send = h2 ? Q[r][b]     : Q[r + 2][b];
                R2[r][b] = keep + __shfl_xor_sync(0xffffffffu, send, 2);
            }
        float hn[NB];
#pragma unroll
        for (int b = 0; b < 4; b++) {
            float keep = h1 ? R2[1][b] : R2[0][b];
            float send = h1 ? R2[0][b] : R2[1][b];
            float u = keep + __shfl_xor_sync(0xffffffffu, send, 1);
            hn[b] = fast_tanh(u + bu_i);
        }

        // ---- LayerNorm reductions: (sum, sumsq) x 4 batches ----
        float r8[8];
#pragma unroll
        for (int b = 0; b < NB; b++) { r8[b] = hn[b]; r8[4 + b] = hn[b] * hn[b]; }
#pragma unroll
        for (int o = 16; o > 0; o >>= 1)
#pragma unroll
            for (int q = 0; q < 8; q++)
                r8[q] += __shfl_xor_sync(0xffffffffu, r8[q], o);
        if (lane == 0) {
#pragma unroll
            for (int q = 0; q < 8; q++) red[warp * 8 + q] = r8[q];
        }
        __syncthreads();   // publishes red; also guards vrow for next-step rewrite

#pragma unroll
        for (int b = 0; b < NB; b++) {
            float s1 = 0.f, s2 = 0.f;
#pragma unroll
            for (int w = 0; w < 8; w++) { s1 += red[w * 8 + b]; s2 += red[w * 8 + 4 + b]; }
            float mu  = s1 * (1.0f / HID);
            float var = fmaf(s2, 1.0f / HID, -mu * mu);
            float hb  = (hn[b] - mu) * rsqrtf(var + EPSV) * g_i + bt_i;
            h[b] = hb;
            col[b][s_out] = fmaf(wn[0], hb, m[b][0]);   // flush leaving slot
            m[b][0] = fmaf(wn[1], hb, m[b][1]);
            m[b][1] = fmaf(wn[2], hb, m[b][2]);
            m[b][2] = fmaf(wn[3], hb, m[b][3]);
            m[b][3] = fmaf(wn[4], hb, m[b][4]);
            m[b][4] = pf[b];
        }
    }

    // ---- output: out[b,:] = h[b] @ W_out^T + b_out ----
#pragma unroll
    for (int b = 0; b < NB; b++) vrow[b * HID + i] = h[b];
    __syncthreads();
    if (tid < 160) {                       // 16 segments x 10 outputs
        int o = tid % 10, seg = tid / 10;
        float a0 = 0.f, a1 = 0.f, a2 = 0.f, a3 = 0.f;
#pragma unroll
        for (int jj = 0; jj < 16; jj++) {
            int ii = seg * 16 + jj;
            float w = W_out[o * HID + ii];
            a0 = fmaf(w, vrow[0 * HID + ii], a0);
            a1 = fmaf(w, vrow[1 * HID + ii], a1);
            a2 = fmaf(w, vrow[2 * HID + ii], a2);
            a3 = fmaf(w, vrow[3 * HID + ii], a3);
        }
        osm[tid * 4 + 0] = a0; osm[tid * 4 + 1] = a1;
        osm[tid * 4 + 2] = a2; osm[tid * 4 + 3] = a3;
    }
    __syncthreads();
    if (tid < NB * 10) {
        int o = tid % 10, b = tid / 10;
        float sum = b_out[o];
#pragma unroll
        for (int seg = 0; seg < 16; seg++)
            sum += osm[(seg * 10 + o) * 4 + b];
        out[(size_t)(b0 + b) * 10 + o] = sum;
    }
}

extern "C" void kernel_launch(void* const* d_in, const int* in_sizes, int n_in,
                              void* d_out, int out_size) {
    (void)in_sizes; (void)n_in; (void)out_size;
    const float* x        = (const float*)d_in[0];
    const float* W_embed  = (const float*)d_in[1];
    const float* b_embed  = (const float*)d_in[2];
    const float* W_update = (const float*)d_in[3];
    const float* b_update = (const float*)d_in[4];
    const float* gamma    = (const float*)d_in[5];
    const float* beta     = (const float*)d_in[6];
    const float* W_out    = (const float*)d_in[7];
    const float* b_out    = (const float*)d_in[8];
    const float* cs       = (const float*)d_in[9];

    const size_t SMEM_BYTES =
        (size_t)(WSROWS * HID + NB * HID + NB * TSTEPS + 320 + 64 + 640)
        * sizeof(float);   // 208,896 B

    cudaFuncSetAttribute(postnorm_rnn_kernel,
                         cudaFuncAttributeMaxDynamicSharedMemorySize,
                         (int)SMEM_BYTES);

    postnorm_rnn_kernel<<<BATCH / NB, NTH, SMEM_BYTES>>>(
        x, W_embed, b_embed, W_update, b_update, gamma, beta,
        W_out, b_out, cs, (float*)d_out);
}

// round 9
// speedup vs baseline: 1.2172x; 1.2172x over previous
#include <cuda_runtime.h>
#include <math.h>

#define HID     256
#define SLOTS   64
#define NB      4
#define TSTEPS  256
#define BATCH   512
#define WSROWS  192          // W rows in SMEM; rows 192-255 via LDG (warps 6,7)
#define NTH     256
#define EPSV    1e-5f

// Slot-memory scratch: 512 x 64 x 256 fp32 = 32 MB (L2-resident)
__device__ float g_mem[(size_t)BATCH * SLOTS * HID];

__device__ __forceinline__ float fast_tanh(float x) {
    float e = __expf(2.0f * x);
    return 1.0f - __fdividef(2.0f, e + 1.0f);
}

#define FFMA2(acc, a, b) \
    asm("fma.rn.f32x2 %0, %1, %2, %0;" : "+l"(acc) : "l"(a), "l"(b))

__global__ void __launch_bounds__(NTH, 1)
postnorm_rnn_kernel(const float* __restrict__ x,        // [512,256,1]
                    const float* __restrict__ W_embed,  // [256]
                    const float* __restrict__ b_embed,  // [256]
                    const float* __restrict__ W_update, // [256,256]
                    const float* __restrict__ b_update, // [256]
                    const float* __restrict__ gamma,    // [256]
                    const float* __restrict__ beta,     // [256]
                    const float* __restrict__ W_out,    // [10,256]
                    const float* __restrict__ b_out,    // [10]
                    const float* __restrict__ cs_in,    // [1]
                    float* __restrict__ out)            // [512,10]
{
    extern __shared__ float smem[];
    float* sW   = smem;                          // 192*256 dense = 49152 f
    float* vrow = sW + WSROWS * HID;             // [b][j] 4*256  =  1024 f
    float* xsm  = vrow + NB * HID;               // [b][t] 4*256  =  1024 f
    float* wtab = xsm + NB * TSTEPS;             // 64*5          =   320 f
    float* red  = wtab + 320;                    // 8 warps x 8   =    64 f
    float* osm  = red + 64;                      // 160*4         =   640 f

    const int tid  = threadIdx.x;
    const int i    = tid;                 // hidden index owned (phase1/LN/mem)
    const int b0   = blockIdx.x * NB;
    const int warp = tid >> 5;
    const int lane = tid & 31;
    const int s    = tid & 7;             // k-slice id (8 slices of 32 k)
    const int rb   = tid & ~7;            // row block: rows rb..rb+7
    const int sK   = s * 4;               // k offset within each 32-float group

    // ---- zero this CTA's slot-memory slice ----
    {
        float4* mz = (float4*)(g_mem + (size_t)b0 * SLOTS * HID);
        for (int k = tid; k < NB * SLOTS * HID / 4; k += NTH)
            mz[k] = make_float4(0.f, 0.f, 0.f, 0.f);
    }
    // ---- stage W_update rows [0,192) dense into SMEM ----
    {
        const float4* Wg = (const float4*)W_update;
        float4*       Ws = (float4*)sW;
        for (int idx = tid; idx < WSROWS * (HID / 4); idx += NTH)
            Ws[idx] = Wg[idx];
    }
    // ---- stage x: xsm[b][t] ----
    {
        int b = tid >> 6, t4 = tid & 63;
        ((float4*)xsm)[tid] =
            ((const float4*)(x + (size_t)(b0 + b) * TSTEPS))[t4];
    }
    // ---- precompute softmax attention-weight table ----
    if (tid < SLOTS) {
        int base = tid;
        float e[5], sum = 0.f;
#pragma unroll
        for (int k = 0; k < 5; k++) {
            int ix = (base + k - 2 + SLOTS) & (SLOTS - 1);
            float d = (float)(ix - base);
            e[k] = expf(-0.125f * d * d);
            sum += e[k];
        }
        float inv = 1.0f / sum;
#pragma unroll
        for (int k = 0; k < 5; k++) wtab[base * 5 + k] = e[k] * inv;
    }

    const float cs   = 1.0f / (1.0f + expf(-cs_in[0]));
    const float We_i = W_embed[i];
    const float be_i = b_embed[i];
    const float bu_i = b_update[i];
    const float g_i  = gamma[i];
    const float bt_i = beta[i];

    float h[NB];
    float m[NB][5];
    float* col[NB];
#pragma unroll
    for (int b = 0; b < NB; b++) {
        h[b] = 0.f;
        col[b] = g_mem + (size_t)(b0 + b) * SLOTS * HID + i;
#pragma unroll
        for (int k = 0; k < 5; k++) m[b][k] = 0.f;
    }

    const bool insm = (rb < WSROWS);      // uniform per warp (rows 192+ = warps 6,7)
    const float* wbase = insm ? (sW + rb * HID + sK)
                              : (W_update + (size_t)rb * HID + sK);
    const float* vbase = vrow + sK;

    __syncthreads();

    for (int t = 0; t < TSTEPS; t++) {
        const int base  = t & (SLOTS - 1);
        const int s_in  = ((base + 3)  & (SLOTS - 1)) * HID;
        const int s_out = ((base + 62) & (SLOTS - 1)) * HID;

        float pf[NB];
#pragma unroll
        for (int b = 0; b < NB; b++) pf[b] = col[b][s_in];

        float wn[5];
#pragma unroll
        for (int k = 0; k < 5; k++) wn[k] = wtab[base * 5 + k];

        // ---- phase 1: v[b] = tanh(x*We+be) + cs*ctx + h[b] ----
#pragma unroll
        for (int b = 0; b < NB; b++) {
            float ctx = 0.f;
#pragma unroll
            for (int k = 0; k < 5; k++) ctx = fmaf(wn[k], m[b][k], ctx);
            vrow[b * HID + i] =
                fast_tanh(fmaf(xsm[b * TSTEPS + t], We_i, be_i)) + cs * ctx + h[b];
        }
        __syncthreads();

        // ---- phase 2: rows rb..rb+7 x 4 batches over k-slice {32jj + 4s + e}
        //      FULLY UNROLLED: all LDS/LDG get immediate offsets, zero IMAD ----
        unsigned long long acc[8][4];
#pragma unroll
        for (int r = 0; r < 8; r++)
#pragma unroll
            for (int b = 0; b < 4; b++) acc[r][b] = 0ull;

        if (insm) {
#pragma unroll
            for (int jj = 0; jj < 8; jj++) {
                const int off = jj * 32;
                ulonglong2 v0 = *(const ulonglong2*)(vbase + 0 * HID + off);
                ulonglong2 v1 = *(const ulonglong2*)(vbase + 1 * HID + off);
                ulonglong2 v2 = *(const ulonglong2*)(vbase + 2 * HID + off);
                ulonglong2 v3 = *(const ulonglong2*)(vbase + 3 * HID + off);
#pragma unroll
                for (int r = 0; r < 8; r++) {
                    ulonglong2 w2 = *(const ulonglong2*)(wbase + r * HID + off);
                    FFMA2(acc[r][0], w2.x, v0.x); FFMA2(acc[r][0], w2.y, v0.y);
                    FFMA2(acc[r][1], w2.x, v1.x); FFMA2(acc[r][1], w2.y, v1.y);
                    FFMA2(acc[r][2], w2.x, v2.x); FFMA2(acc[r][2], w2.y, v2.y);
                    FFMA2(acc[r][3], w2.x, v3.x); FFMA2(acc[r][3], w2.y, v3.y);
                }
            }
        } else {
#pragma unroll
            for (int jj = 0; jj < 8; jj++) {
                const int off = jj * 32;
                ulonglong2 v0 = *(const ulonglong2*)(vbase + 0 * HID + off);
                ulonglong2 v1 = *(const ulonglong2*)(vbase + 1 * HID + off);
                ulonglong2 v2 = *(const ulonglong2*)(vbase + 2 * HID + off);
                ulonglong2 v3 = *(const ulonglong2*)(vbase + 3 * HID + off);
#pragma unroll
                for (int r = 0; r < 8; r++) {
                    ulonglong2 w2 = __ldg((const ulonglong2*)(wbase + r * HID + off));
                    FFMA2(acc[r][0], w2.x, v0.x); FFMA2(acc[r][0], w2.y, v0.y);
                    FFMA2(acc[r][1], w2.x, v1.x); FFMA2(acc[r][1], w2.y, v1.y);
                    FFMA2(acc[r][2], w2.x, v2.x); FFMA2(acc[r][2], w2.y, v2.y);
                    FFMA2(acc[r][3], w2.x, v3.x); FFMA2(acc[r][3], w2.y, v3.y);
                }
            }
        }

        // ---- unpack partials: P[r][b] over this thread's 32-k slice ----
        float P[8][4];
#pragma unroll
        for (int r = 0; r < 8; r++)
#pragma unroll
            for (int b = 0; b < 4; b++) {
                float lo = __uint_as_float((unsigned)(acc[r][b] & 0xffffffffu));
                float hi = __uint_as_float((unsigned)(acc[r][b] >> 32));
                P[r][b] = lo + hi;
            }

        // ---- routed butterfly over 8 k-slices: lane ends with row rb+s ----
        const bool h4 = (s & 4), h2 = (s & 2), h1 = (s & 1);
        float Q[4][4];
#pragma unroll
        for (int r = 0; r < 4; r++)
#pragma unroll
            for (int b = 0; b < 4; b++) {
                float keep = h4 ? P[r + 4][b] : P[r][b];
                float send = h4 ? P[r][b]     : P[r + 4][b];
                Q[r][b] = keep + __shfl_xor_sync(0xffffffffu, send, 4);
            }
        float R2[2][4];
#pragma unroll
        for (int r = 0; r < 2; r++)
#pragma unroll
            for (int b = 0; b < 4; b++) {
                float keep = h2 ? Q[r + 2][b] : Q[r][b];
                float send = h2 ? Q[r][b]     : Q[r + 2][b];
                R2[r][b] = keep + __shfl_xor_sync(0xffffffffu, send, 2);
            }
        float hn[NB];
#pragma unroll
        for (int b = 0; b < 4; b++) {
            float keep = h1 ? R2[1][b] : R2[0][b];
            float send = h1 ? R2[0][b] : R2[1][b];
            float u = keep + __shfl_xor_sync(0xffffffffu, send, 1);
            hn[b] = fast_tanh(u + bu_i);
        }

        // ---- LayerNorm reductions: (sum, sumsq) x 4 batches ----
        float r8[8];
#pragma unroll
        for (int b = 0; b < NB; b++) { r8[b] = hn[b]; r8[4 + b] = hn[b] * hn[b]; }
#pragma unroll
        for (int o = 16; o > 0; o >>= 1)
#pragma unroll
            for (int q = 0; q < 8; q++)
                r8[q] += __shfl_xor_sync(0xffffffffu, r8[q], o);
        if (lane == 0) {
#pragma unroll
            for (int q = 0; q < 8; q++) red[warp * 8 + q] = r8[q];
        }
        __syncthreads();   // publishes red; also guards vrow for next-step rewrite

#pragma unroll
        for (int b = 0; b < NB; b++) {
            float s1 = 0.f, s2 = 0.f;
#pragma unroll
            for (int w = 0; w < 8; w++) { s1 += red[w * 8 + b]; s2 += red[w * 8 + 4 + b]; }
            float mu  = s1 * (1.0f / HID);
            float var = fmaf(s2, 1.0f / HID, -mu * mu);
            float hb  = (hn[b] - mu) * rsqrtf(var + EPSV) * g_i + bt_i;
            h[b] = hb;
            col[b][s_out] = fmaf(wn[0], hb, m[b][0]);   // flush leaving slot
            m[b][0] = fmaf(wn[1], hb, m[b][1]);
            m[b][1] = fmaf(wn[2], hb, m[b][2]);
            m[b][2] = fmaf(wn[3], hb, m[b][3]);
            m[b][3] = fmaf(wn[4], hb, m[b][4]);
            m[b][4] = pf[b];
        }
    }

    // ---- output: out[b,:] = h[b] @ W_out^T + b_out ----
#pragma unroll
    for (int b = 0; b < NB; b++) vrow[b * HID + i] = h[b];
    __syncthreads();
    if (tid < 160) {                       // 16 segments x 10 outputs
        int o = tid % 10, seg = tid / 10;
        float a0 = 0.f, a1 = 0.f, a2 = 0.f, a3 = 0.f;
#pragma unroll
        for (int jj = 0; jj < 16; jj++) {
            int ii = seg * 16 + jj;
            float w = W_out[o * HID + ii];
            a0 = fmaf(w, vrow[0 * HID + ii], a0);
            a1 = fmaf(w, vrow[1 * HID + ii], a1);
            a2 = fmaf(w, vrow[2 * HID + ii], a2);
            a3 = fmaf(w, vrow[3 * HID + ii], a3);
        }
        osm[tid * 4 + 0] = a0; osm[tid * 4 + 1] = a1;
        osm[tid * 4 + 2] = a2; osm[tid * 4 + 3] = a3;
    }
    __syncthreads();
    if (tid < NB * 10) {
        int o = tid % 10, b = tid / 10;
        float sum = b_out[o];
#pragma unroll
        for (int seg = 0; seg < 16; seg++)
            sum += osm[(seg * 10 + o) * 4 + b];
        out[(size_t)(b0 + b) * 10 + o] = sum;
    }
}

extern "C" void kernel_launch(void* const* d_in, const int* in_sizes, int n_in,
                              void* d_out, int out_size) {
    (void)in_sizes; (void)n_in; (void)out_size;
    const float* x        = (const float*)d_in[0];
    const float* W_embed  = (const float*)d_in[1];
    const float* b_embed  = (const float*)d_in[2];
    const float* W_update = (const float*)d_in[3];
    const float* b_update = (const float*)d_in[4];
    const float* gamma    = (const float*)d_in[5];
    const float* beta     = (const float*)d_in[6];
    const float* W_out    = (const float*)d_in[7];
    const float* b_out    = (const float*)d_in[8];
    const float* cs       = (const float*)d_in[9];

    const size_t SMEM_BYTES =
        (size_t)(WSROWS * HID + NB * HID + NB * TSTEPS + 320 + 64 + 640)
        * sizeof(float);   // 208,896 B

    cudaFuncSetAttribute(postnorm_rnn_kernel,
                         cudaFuncAttributeMaxDynamicSharedMemorySize,
                         (int)SMEM_BYTES);

    postnorm_rnn_kernel<<<BATCH / NB, NTH, SMEM_BYTES>>>(
        x, W_embed, b_embed, W_update, b_update, gamma, beta,
        W_out, b_out, cs, (float*)d_out);
}